// round 12
// baseline (speedup 1.0000x reference)
#include <cuda_runtime.h>
#include <cuda_bf16.h>
#include <cstdint>

// ============================================================================
// Problem constants
// ============================================================================
#define NQ      4096
#define NREF    65536
#define DIMK    512
#define TOPK    16
#define NCTA    148                    // persistent CTAs (one wave)
#define MBLK    64                     // queries per CTA tile
#define NMB     (NQ / MBLK)            // 64 query mblocks
#define SPANS_PER_MB 64                // span = 1024 refs = 4 tiles of 256
#define TOTAL_UNITS (NMB * SPANS_PER_MB)   // 4096
#define E_SLOTS 8                      // max CTAs covering one mblock
#define NSQUAD  8                      // scanner threads per query row

// SMEM layout (byte offsets into dynamic smem)
#define SM_A      0                    // 64 x 512 bf16 (swizzled rows)     65536
#define SM_B      65536                // 2 x (256 x 128 bf16 swizzled)    131072
#define SM_STAGE  196608               // 64 x 128 fp32 (swizzled)          32768
#define SM_BAR    229376               // mbar[0],mbar[1] = B bufs; mbar[2] = A
#define SMEM_TOTAL 229408

// ============================================================================
// Scratch (static device arrays; no allocation anywhere)
//   g_refs_sw: tile-swizzled refs: [T2:256 (256-ref tile)][kc:4][64KB block]
//              block layout: row*256 + ((col*2) ^ ((row&7)<<4)), col = k%128
//   g_xn_sw  : swizzled queries:   [mb:64][64KB block]
//              block layout: row*1024 + ((k*2) ^ ((row&7)<<4))
// ============================================================================
__device__ __align__(16) __nv_bfloat16 g_refs_sw[(size_t)NREF * DIMK]; // 64 MB
__device__ __align__(16) __nv_bfloat16 g_xn_sw[(size_t)NQ * DIMK];     // 4 MB
__device__ __align__(16) float g_part[(size_t)NQ * E_SLOTS * NSQUAD * TOPK]; // 16 MB

// ============================================================================
// Helpers (baseline sm_103 ISA only — bulk copy is sm_90 baseline, OK)
// ============================================================================
__device__ __forceinline__ uint32_t smem_u32(const void* p) {
    return (uint32_t)__cvta_generic_to_shared(p);
}

#define MBARRIER_INIT(addr, count) \
    asm volatile("mbarrier.init.shared.b64 [%0], %1;" :: "r"((uint32_t)(addr)), "r"((uint32_t)(count)) : "memory")

#define MBARRIER_EXPECT_TX(addr, bytes) \
    asm volatile("mbarrier.arrive.expect_tx.shared.b64 _, [%0], %1;" \
                 :: "r"((uint32_t)(addr)), "r"((uint32_t)(bytes)) : "memory")

#define MBARRIER_WAIT_PARITY(mbar_smem_addr, phase_parity) do { \
    uint32_t _mbar = (uint32_t)(mbar_smem_addr); \
    uint32_t _parity = (uint32_t)(phase_parity); \
    uint32_t _done; \
    asm volatile( \
        "{\n\t" \
        ".reg .pred p;\n\t" \
        "mbarrier.try_wait.parity.acquire.cta.shared::cta.b64 p, [%1], %2;\n\t" \
        "selp.b32 %0, 1, 0, p;\n\t" \
        "}" \
        : "=r"(_done) : "r"(_mbar), "r"(_parity) : "memory"); \
    if (!_done) { \
        asm volatile( \
            "{\n\t" \
            ".reg .pred P1;\n\t" \
            "WAIT_LOOP_%=:\n\t" \
            "mbarrier.try_wait.parity.acquire.cta.shared::cta.b64 P1, [%0], %1, 0x989680;\n\t" \
            "@P1 bra.uni WAIT_DONE_%=;\n\t" \
            "bra.uni WAIT_LOOP_%=;\n\t" \
            "WAIT_DONE_%=:\n\t" \
            "}" \
            :: "r"(_mbar), "r"(_parity) : "memory"); \
    } \
} while (0)

// One-instruction bulk global->shared copy with mbarrier completion
__device__ __forceinline__ void bulk_g2s(uint32_t dst, const void* src,
                                         uint32_t bytes, uint32_t mbar) {
    asm volatile(
        "cp.async.bulk.shared::cluster.global.mbarrier::complete_tx::bytes [%0], [%1], %2, [%3];"
        :: "r"(dst), "l"((unsigned long long)__cvta_generic_to_global(src)),
           "r"(bytes), "r"(mbar) : "memory");
}

__device__ __forceinline__ void ldsm_x4(uint32_t* r, uint32_t addr) {
    asm volatile("ldmatrix.sync.aligned.m8n8.x4.shared.b16 {%0,%1,%2,%3}, [%4];"
                 : "=r"(r[0]), "=r"(r[1]), "=r"(r[2]), "=r"(r[3]) : "r"(addr));
}

__device__ __forceinline__ void mma16816(float* c, const uint32_t* a, const uint32_t* b) {
    asm volatile("mma.sync.aligned.m16n8k16.row.col.f32.bf16.bf16.f32 "
                 "{%0,%1,%2,%3}, {%4,%5,%6,%7}, {%8,%9}, {%0,%1,%2,%3};"
                 : "+f"(c[0]), "+f"(c[1]), "+f"(c[2]), "+f"(c[3])
                 : "r"(a[0]), "r"(a[1]), "r"(a[2]), "r"(a[3]), "r"(b[0]), "r"(b[1]));
}

__device__ __forceinline__ void topk_insert(float v, float* top, float& thr) {
    if (v > thr) {
        int mi = 0; float mv = top[0];
#pragma unroll
        for (int i = 1; i < TOPK; i++)
            if (top[i] < mv) { mv = top[i]; mi = i; }
        top[mi] = v;
        mv = top[0];
#pragma unroll
        for (int i = 1; i < TOPK; i++) mv = fminf(mv, top[i]);
        thr = mv;
    }
}

// Balanced static partition of TOTAL_UNITS over NCTA CTAs
__device__ __forceinline__ int unit_begin(int c) { return (c * TOTAL_UNITS) / NCTA; }
__device__ __forceinline__ int cta_of_unit(int u) {
    int c = (u * NCTA) / TOTAL_UNITS;
    while (unit_begin(c + 1) <= u) c++;
    while (unit_begin(c) > u) c--;
    return c;
}

// ============================================================================
// Kernel 1: L2-normalize x (fp32) -> g_xn_sw (bf16, pre-swizzled layout)
// ============================================================================
__global__ void k_norm(const float* __restrict__ x) {
    int row = blockIdx.x;
    int tid = threadIdx.x;   // 128; thread handles k = 4*tid .. 4*tid+3
    float4 v = ((const float4*)(x + (size_t)row * DIMK))[tid];
    float ss = v.x * v.x + v.y * v.y + v.z * v.z + v.w * v.w;
#pragma unroll
    for (int o = 16; o; o >>= 1) ss += __shfl_xor_sync(0xFFFFFFFFu, ss, o);
    __shared__ float sred[4];
    if ((tid & 31) == 0) sred[tid >> 5] = ss;
    __syncthreads();
    float tot = sred[0] + sred[1] + sred[2] + sred[3];
    float inv = 1.0f / fmaxf(sqrtf(tot), 1e-12f);
    __nv_bfloat162 p0 = __floats2bfloat162_rn(v.x * inv, v.y * inv);
    __nv_bfloat162 p1 = __floats2bfloat162_rn(v.z * inv, v.w * inv);
    int mb = row >> 6, mrow = row & 63;
    uint32_t off = ((uint32_t)(8 * tid)) ^ ((uint32_t)(mrow & 7) << 4);
    char* dst = (char*)g_xn_sw + (size_t)mb * 65536 + (size_t)mrow * 1024 + off;
    uint2 pk;
    pk.x = *(uint32_t*)&p0;
    pk.y = *(uint32_t*)&p1;
    *(uint2*)dst = pk;
}

// ============================================================================
// Kernel 2: refs fp32 -> bf16, written directly in tile-swizzled layout
// ============================================================================
__global__ void k_cvt(const float* __restrict__ refs) {
    int n4 = NREF * DIMK / 4;
    const float4* src = (const float4*)refs;
    for (int i = blockIdx.x * blockDim.x + threadIdx.x; i < n4; i += gridDim.x * blockDim.x) {
        float4 v = src[i];
        int n = i >> 7;            // ref row
        int kq = i & 127;          // float4 index within row (k = 4*kq)
        int T2 = n >> 8, row = n & 255;
        int kc = kq >> 5;          // 128-col k-block
        uint32_t col2 = (uint32_t)(8 * (kq & 31));
        uint32_t off = col2 ^ ((uint32_t)(row & 7) << 4);
        char* dst = (char*)g_refs_sw + ((size_t)(T2 * 4 + kc)) * 65536
                  + (size_t)row * 256 + off;
        __nv_bfloat162 p0 = __floats2bfloat162_rn(v.x, v.y);
        __nv_bfloat162 p1 = __floats2bfloat162_rn(v.z, v.w);
        uint2 pk;
        pk.x = *(uint32_t*)&p0;
        pk.y = *(uint32_t*)&p1;
        *(uint2*)dst = pk;
    }
}

// ============================================================================
// Kernel 2b: reset partial-list slots to -2 (required every graph replay)
// ============================================================================
__global__ void k_fill() {
    int i = blockIdx.x * blockDim.x + threadIdx.x;
    ((float4*)g_part)[i] = make_float4(-2.f, -2.f, -2.f, -2.f);
}

// ============================================================================
// Kernel 3: persistent bf16 mma.sync GEMM + fused streaming top-16
//   148 CTAs x 512 threads (16 warps: 2M x 8N of 32x32 warp tiles)
//   CTA tile 64(M) x 256(N) x 128(K-chunk); B via single cp.async.bulk
// ============================================================================
__global__ __launch_bounds__(512, 1) void k_main() {
    extern __shared__ char smem[];
    const uint32_t sb = smem_u32(smem);
    const int tid = threadIdx.x, wid = tid >> 5, lid = tid & 31;
    const int mw = wid >> 3, nw = wid & 7;
    const int c = blockIdx.x;

    // ---- per-lane ldmatrix address components -------------------------------
    const uint32_t swz = (uint32_t)(lid & 7) << 4;
    const int sub = lid >> 3;
    const int aRow = mw * 32 + (lid & 7) + ((sub & 1) << 3);
    const uint32_t a_kof2 = (uint32_t)(sub >> 1) << 4;
    const uint32_t aBase = sb + SM_A + (uint32_t)aRow * 1024u;
    const int bRow = nw * 32 + (lid & 7) + ((sub >> 1) << 3);
    const uint32_t b_kof2 = (uint32_t)(sub & 1) << 4;
    const uint32_t bRowByte = (uint32_t)bRow * 256u;

    const int srow = tid & 63, squad = tid >> 6;         // scanner mapping
    const uint32_t s_swz = (uint32_t)(srow & 7) << 4;
    const int s_rot = (srow >> 3) & 3;                   // conflict-spread rotation

    // ---- mbarrier init ------------------------------------------------------
    if (tid == 0) {
        MBARRIER_INIT(sb + SM_BAR + 0, 1);
        MBARRIER_INIT(sb + SM_BAR + 8, 1);
        MBARRIER_INIT(sb + SM_BAR + 16, 1);
    }
    __syncthreads();
    uint32_t phB0 = 0, phB1 = 0, phA = 0;

    int u = unit_begin(c);
    const int u_end = unit_begin(c + 1);

#pragma unroll 1
    while (u < u_end) {
        const int mb = u >> 6;
        const int seg_end = min(u_end, (mb + 1) << 6);
        const int nch = (seg_end - u) * 16;              // 16 chunks per span
        const int span0 = u & 63;

        // ---- issue A tile bulk + B chunk 0 bulk ------------------------------
        if (tid == 0) {
            MBARRIER_EXPECT_TX(sb + SM_BAR + 16, 65536u);
            bulk_g2s(sb + SM_A, (const char*)g_xn_sw + (size_t)mb * 65536,
                     65536u, sb + SM_BAR + 16);
            int T0 = span0 * 4;                          // chunk 0: tile span0*4, kc 0
            MBARRIER_EXPECT_TX(sb + SM_BAR + 0, 65536u);
            bulk_g2s(sb + SM_B, (const char*)g_refs_sw + ((size_t)T0 * 4) * 65536,
                     65536u, sb + SM_BAR + 0);
        }
        MBARRIER_WAIT_PARITY(sb + SM_BAR + 16, phA);
        phA ^= 1;

        // ---- reinit state ----------------------------------------------------
        float acc[2][4][4];
#pragma unroll
        for (int a = 0; a < 2; a++)
#pragma unroll
            for (int b = 0; b < 4; b++)
#pragma unroll
                for (int d = 0; d < 4; d++) acc[a][b][d] = 0.f;
        float top[TOPK];
#pragma unroll
        for (int i = 0; i < TOPK; i++) top[i] = -2.0f;
        float thr = -2.0f;

#pragma unroll 1
        for (int ch = 0; ch < nch; ch++) {
            // ---- producer: single bulk for chunk ch+1 ------------------------
            if (tid == 0 && ch + 1 < nch) {
                int ch2 = ch + 1;
                int s2 = span0 + (ch2 >> 4);
                int T2 = s2 * 4 + ((ch2 >> 2) & 3);
                int kc2 = ch2 & 3;
                uint32_t mbar = sb + SM_BAR + (uint32_t)(ch2 & 1) * 8u;
                MBARRIER_EXPECT_TX(mbar, 65536u);
                bulk_g2s(sb + SM_B + (uint32_t)(ch2 & 1) * 65536u,
                         (const char*)g_refs_sw + ((size_t)(T2 * 4 + kc2)) * 65536,
                         65536u, mbar);
            }
            // ---- wait current chunk ------------------------------------------
            if (ch & 1) { MBARRIER_WAIT_PARITY(sb + SM_BAR + 8, phB1); phB1 ^= 1; }
            else        { MBARRIER_WAIT_PARITY(sb + SM_BAR + 0, phB0); phB0 ^= 1; }

            // ---- compute chunk ch: K=128 = 8 mma k-steps ---------------------
            {
                const uint32_t aoff = (uint32_t)(ch & 3) * 256u;   // k-block in A row
                const uint32_t bbase = sb + SM_B + (uint32_t)(ch & 1) * 65536u + bRowByte;
                uint32_t afr[2][4];
                uint32_t bfr[2][4];
#pragma unroll
                for (int ks = 0; ks < 8; ks++) {
                    uint32_t ko = (uint32_t)ks * 32u;
#pragma unroll
                    for (int mt = 0; mt < 2; mt++)
                        ldsm_x4(afr[mt], aBase + (uint32_t)mt * 16384u +
                                ((aoff + ko + a_kof2) ^ swz));
#pragma unroll
                    for (int j = 0; j < 2; j++)
                        ldsm_x4(bfr[j], bbase + (uint32_t)j * 4096u +
                                ((ko + b_kof2) ^ swz));
#pragma unroll
                    for (int mt = 0; mt < 2; mt++)
#pragma unroll
                        for (int nt = 0; nt < 4; nt++)
                            mma16816(acc[mt][nt], afr[mt], &bfr[nt >> 1][(nt & 1) * 2]);
                }
            }

            // ---- epilogue every 4 chunks (one 64x256 dot tile done) ----------
            if ((ch & 3) == 3) {
#pragma unroll 1
                for (int p = 0; p < 2; p++) {
                    if ((nw >> 2) == p) {
                        int colbase = (nw & 3) * 32;
#pragma unroll
                        for (int mt = 0; mt < 2; mt++) {
#pragma unroll
                            for (int nt = 0; nt < 4; nt++) {
                                int r0 = mw * 32 + mt * 16 + (lid >> 2);
                                uint32_t cb = (uint32_t)((colbase + nt * 8 + 2 * (lid & 3)) * 4);
                                char* base0 = smem + SM_STAGE + r0 * 512;
                                char* base1 = base0 + 8 * 512;
                                *(float2*)(base0 + (cb ^ ((uint32_t)(r0 & 7) << 4))) =
                                    make_float2(acc[mt][nt][0], acc[mt][nt][1]);
                                *(float2*)(base1 + (cb ^ ((uint32_t)((r0 + 8) & 7) << 4))) =
                                    make_float2(acc[mt][nt][2], acc[mt][nt][3]);
                            }
                        }
                    }
                    __syncthreads();
                    // scan: thread (srow, squad) reads its 16 columns (4 float4)
                    {
                        const char* base = smem + SM_STAGE + srow * 512;
#pragma unroll
                        for (int jj = 0; jj < 4; jj++) {
                            uint32_t jr = (uint32_t)((jj + s_rot) & 3);
                            uint32_t off = ((uint32_t)(squad * 64) + jr * 16u) ^ s_swz;
                            float4 v = *(const float4*)(base + off);
                            topk_insert(v.x, top, thr);
                            topk_insert(v.y, top, thr);
                            topk_insert(v.z, top, thr);
                            topk_insert(v.w, top, thr);
                        }
                    }
                    __syncthreads();
                }
#pragma unroll
                for (int a = 0; a < 2; a++)
#pragma unroll
                    for (int b = 0; b < 4; b++)
#pragma unroll
                        for (int d = 0; d < 4; d++) acc[a][b][d] = 0.f;
            } else {
                __syncthreads();
            }
        }

        // ---- flush running top-16 for this mblock episode --------------------
        {
            int e = c - cta_of_unit(mb << 6);            // < E_SLOTS by construction
            float* dst = g_part + (((size_t)(mb * MBLK + srow) * E_SLOTS + e) * NSQUAD
                       + squad) * TOPK;
#pragma unroll
            for (int i = 0; i < TOPK; i++) dst[i] = top[i];
        }
        u = seg_end;
    }
}

// ============================================================================
// Kernel 4: merge E_SLOTS x NSQUAD partial top-16s -> final sorted weights
// ============================================================================
__global__ void k_merge(float* __restrict__ out) {
    int q = blockIdx.x * blockDim.x + threadIdx.x;
    if (q >= NQ) return;
    float top[TOPK];
#pragma unroll
    for (int i = 0; i < TOPK; i++) top[i] = -2.0f;
    float thr = -2.0f;
    const float4* src = (const float4*)g_part + (size_t)q * (E_SLOTS * NSQUAD * TOPK / 4);
#pragma unroll 1
    for (int b = 0; b < E_SLOTS * NSQUAD * TOPK / 4; b += 8) {
        float4 v[8];
#pragma unroll
        for (int j = 0; j < 8; j++) v[j] = src[b + j];
#pragma unroll
        for (int j = 0; j < 8; j++) {
            topk_insert(v[j].x, top, thr);
            topk_insert(v[j].y, top, thr);
            topk_insert(v[j].z, top, thr);
            topk_insert(v[j].w, top, thr);
        }
    }
    // sort dots descending (= ascending distance, matching top_k order)
#pragma unroll 1
    for (int a = 0; a < TOPK - 1; a++) {
        int bi = a; float bv = top[a];
#pragma unroll 1
        for (int b = a + 1; b < TOPK; b++)
            if (top[b] > bv) { bv = top[b]; bi = b; }
        top[bi] = top[a]; top[a] = bv;
    }
    float w[TOPK];
    float s = 0.f;
#pragma unroll
    for (int j = 0; j < TOPK; j++) {
        float d2 = fmaxf(2.0f - 2.0f * top[j], 1e-12f);
        float d = sqrtf(d2);
        float wv = expf(-d);
        w[j] = wv; s += wv;
    }
    float inv = 1.0f / fmaxf(s, 1e-12f);
#pragma unroll
    for (int j = 0; j < TOPK; j++) out[(size_t)q * TOPK + j] = w[j] * inv;
}

// ============================================================================
// Launch
// ============================================================================
extern "C" void kernel_launch(void* const* d_in, const int* in_sizes, int n_in,
                              void* d_out, int out_size) {
    const float* x    = (const float*)d_in[0];
    const float* refs = (const float*)d_in[1];
    float* out = (float*)d_out;

    k_norm<<<NQ, 128>>>(x);
    k_cvt<<<2048, 256>>>(refs);
    k_fill<<<(NQ * E_SLOTS * NSQUAD * TOPK / 4) / 256, 256>>>();
    cudaFuncSetAttribute(k_main, cudaFuncAttributeMaxDynamicSharedMemorySize, SMEM_TOTAL);
    k_main<<<NCTA, 512, SMEM_TOTAL>>>();
    k_merge<<<NQ / 128, 128>>>(out);
}